// round 3
// baseline (speedup 1.0000x reference)
#include <cuda_runtime.h>

#define Bn 4
#define Cn 16
#define Kn 100
#define Pn 76800
#define ITERS 10
#define BW2F ((float)(0.16*0.16))

#define TPB 128
#define IPT 2                    // points per thread (1 packed pair)
#define XB  (Pn/(TPB*IPT))       // 300
#define ZS  4                    // k-split
#define KQ  (Kn/ZS)              // 25

typedef unsigned long long u64;

// ---- device scratch (static; no allocations) ----
__device__ float g_ms[ITERS+1][Bn*Kn*Cn];   // means entering iteration t (t=0 = seeds)
__device__ float g_num[ITERS][Bn*Kn*Cn];
__device__ float g_den[ITERS][Bn*Kn];
__device__ u64   g_best[Bn*Pn];             // packed (ordered dist bits << 32) | k
__device__ int   g_is64;

// ---- packed f32x2 helpers ----
__device__ __forceinline__ u64 pk2(float lo, float hi) {
    u64 r; asm("mov.b64 %0,{%1,%2};" : "=l"(r) : "f"(lo), "f"(hi)); return r;
}
__device__ __forceinline__ void up2(u64 v, float& lo, float& hi) {
    asm("mov.b64 {%0,%1},%2;" : "=f"(lo), "=f"(hi) : "l"(v));
}
__device__ __forceinline__ u64 f2fma(u64 a, u64 b, u64 c) {
    u64 d; asm("fma.rn.f32x2 %0,%1,%2,%3;" : "=l"(d) : "l"(a), "l"(b), "l"(c)); return d;
}
__device__ __forceinline__ u64 f2mul(u64 a, u64 b) {
    u64 d; asm("mul.rn.f32x2 %0,%1,%2;" : "=l"(d) : "l"(a), "l"(b)); return d;
}
__device__ __forceinline__ u64 f2add(u64 a, u64 b) {
    u64 d; asm("add.rn.f32x2 %0,%1,%2;" : "=l"(d) : "l"(a), "l"(b)); return d;
}
// order-preserving float -> uint map (strictly monotone)
__device__ __forceinline__ unsigned obits(float f) {
    unsigned u = __float_as_uint(f);
    return (u & 0x80000000u) ? ~u : (u | 0x80000000u);
}

// ---------------------------------------------------------------------------
// int64 vs int32 seed_idx detection (first 1600 bytes valid for both layouts)
// ---------------------------------------------------------------------------
__global__ void detect_idx_kernel(const void* idxraw) {
    __shared__ int bad;
    if (threadIdx.x == 0) bad = 0;
    __syncthreads();
    const long long* p = (const long long*)idxraw;
    for (int i = threadIdx.x; i < 200; i += blockDim.x) {
        long long v = p[i];
        if (v < 0 || v >= (long long)Pn) bad = 1;
    }
    __syncthreads();
    if (threadIdx.x == 0) g_is64 = bad ? 0 : 1;
}

// ---------------------------------------------------------------------------
// Init: zero all per-iteration accumulators, reset g_best, gather seed means.
// ---------------------------------------------------------------------------
__global__ void init_kernel(const float* __restrict__ feat,
                            const void* __restrict__ idxraw) {
    int t = blockIdx.x * blockDim.x + threadIdx.x;
    int stride = gridDim.x * blockDim.x;
    for (int i = t; i < Bn * Pn; i += stride) g_best[i] = ~0ull;
    float* num0 = &g_num[0][0];
    for (int i = t; i < ITERS * Bn * Kn * Cn; i += stride) num0[i] = 0.0f;
    float* den0 = &g_den[0][0];
    for (int i = t; i < ITERS * Bn * Kn; i += stride) den0[i] = 0.0f;

    if (t < Bn * Kn) {
        int b = t / Kn;
        long long idx;
        if (g_is64) idx = ((const long long*)idxraw)[t];
        else        idx = (long long)((const int*)idxraw)[t];
        const float* fb = feat + (size_t)b * Cn * Pn + (size_t)idx;
#pragma unroll
        for (int c = 0; c < Cn; c++)
            g_ms[0][t * Cn + c] = fb[(size_t)c * Pn];
    }
}

// ---------------------------------------------------------------------------
// One pass over all points for one k-quarter.
//   iter in [0,10): accumulate masked sums into g_num/g_den[iter]
//   iter == 10:     label pass -> atomicMin of packed (dist,k) into g_best
// smem means are pre-scaled by -2 (exact) so dist = (fn2+mn2) + sum f*m'.
// ---------------------------------------------------------------------------
__global__ void __launch_bounds__(TPB, 6)
pass_kernel(const float* __restrict__ feat, int iter) {
    __shared__ __align__(16) u64 s_m2[KQ * Cn];   // {-2m,-2m} duplicated
    __shared__ u64 s_mn2[KQ];                     // {mn2,mn2}
    const int b = blockIdx.y;
    const int k0 = blockIdx.z * KQ;

    // ---- update phase: build means for this k-quarter ----
    for (int kl = threadIdx.x; kl < KQ; kl += TPB) {
        int kg = k0 + kl;
        int base = (b * Kn + kg) * Cn;
        float mn2 = 0.0f;
        if (iter == 0) {
#pragma unroll
            for (int c = 0; c < Cn; c++) {
                float m = g_ms[0][base + c];
                float m2 = -2.0f * m;
                s_m2[kl * Cn + c] = pk2(m2, m2);
                mn2 += m * m;
            }
        } else {
            float den = g_den[iter - 1][b * Kn + kg];
            float dm = fmaxf(den, 1.0f);
            bool pos = den > 0.0f;
#pragma unroll
            for (int c = 0; c < Cn; c++) {
                float old = g_ms[iter - 1][base + c];
                float nm = pos ? (g_num[iter - 1][base + c] / dm) : old;
                float m2 = -2.0f * nm;
                s_m2[kl * Cn + c] = pk2(m2, m2);
                mn2 += nm * nm;
                if (blockIdx.x == 0) g_ms[iter][base + c] = nm;
            }
        }
        s_mn2[kl] = pk2(mn2, mn2);
    }
    __syncthreads();

    // ---- load 2 consecutive points as 1 packed pair (channels via LDG.64) ----
    const int pbase = blockIdx.x * (TPB * IPT) + 2 * threadIdx.x;
    const u64* fb2 = (const u64*)(feat + (size_t)b * Cn * Pn + pbase);
    u64 fp[Cn];
    u64 fn2 = 0;
#pragma unroll
    for (int c = 0; c < Cn; c++) {
        u64 v = fb2[(size_t)c * (Pn / 2)];
        fp[c] = v;
        fn2 = c ? f2fma(v, v, fn2) : f2mul(v, v);
    }

    const bool lab = (iter == ITERS);
    float best0 = 3.4e38f, best1 = 3.4e38f;
    int bidx0 = 0, bidx1 = 0;

    for (int kl = 0; kl < KQ; kl++) {
        const ulonglong2* mp = (const ulonglong2*)&s_m2[kl * Cn];
        // first half: channels 0..7 (keeps only 16 mean regs live at a time)
        ulonglong2 m01 = mp[0], m23 = mp[1], m45 = mp[2], m67 = mp[3];
        u64 base01 = f2add(fn2, s_mn2[kl]);        // fn2 + mn2
        u64 a0 = f2fma(fp[0], m01.x, base01);
        u64 a1 = f2mul(fp[1], m01.y);
        u64 a2 = f2mul(fp[2], m23.x);
        u64 a3 = f2mul(fp[3], m23.y);
        a0 = f2fma(fp[4], m45.x, a0);
        a1 = f2fma(fp[5], m45.y, a1);
        a2 = f2fma(fp[6], m67.x, a2);
        a3 = f2fma(fp[7], m67.y, a3);
        // second half: channels 8..15
        ulonglong2 m89 = mp[4], mab = mp[5], mcd = mp[6], mef = mp[7];
        a0 = f2fma(fp[8],  m89.x, a0);
        a1 = f2fma(fp[9],  m89.y, a1);
        a2 = f2fma(fp[10], mab.x, a2);
        a3 = f2fma(fp[11], mab.y, a3);
        a0 = f2fma(fp[12], mcd.x, a0);
        a1 = f2fma(fp[13], mcd.y, a1);
        a2 = f2fma(fp[14], mef.x, a2);
        a3 = f2fma(fp[15], mef.y, a3);
        u64 dist = f2add(f2add(a0, a1), f2add(a2, a3));
        float dlo, dhi;
        up2(dist, dlo, dhi);

        if (!lab) {
            if (fminf(dlo, dhi) < BW2F) {           // rare path
                int kg = k0 + kl;
                if (dlo < BW2F) {
                    atomicAdd(&g_den[iter][b * Kn + kg], 1.0f);
#pragma unroll
                    for (int c = 0; c < Cn; c++) {
                        float v0, v1; up2(fp[c], v0, v1);
                        atomicAdd(&g_num[iter][(b * Kn + kg) * Cn + c], v0);
                    }
                }
                if (dhi < BW2F) {
                    atomicAdd(&g_den[iter][b * Kn + kg], 1.0f);
#pragma unroll
                    for (int c = 0; c < Cn; c++) {
                        float v0, v1; up2(fp[c], v0, v1);
                        atomicAdd(&g_num[iter][(b * Kn + kg) * Cn + c], v1);
                    }
                }
            }
        } else {
            if (dlo < best0) { best0 = dlo; bidx0 = k0 + kl; }
            if (dhi < best1) { best1 = dhi; bidx1 = k0 + kl; }
        }
    }

    if (lab) {
        u64 v0 = ((u64)obits(best0) << 32) | (unsigned)bidx0;
        u64 v1 = ((u64)obits(best1) << 32) | (unsigned)bidx1;
        atomicMin(&g_best[b * Pn + pbase],     v0);
        atomicMin(&g_best[b * Pn + pbase + 1], v1);
    }
}

// ---------------------------------------------------------------------------
// Finalize: labels from g_best; converged means (g_ms[10]) to the tail.
// ---------------------------------------------------------------------------
__global__ void finalize_kernel(float* __restrict__ out, int out_size) {
    int t = blockIdx.x * blockDim.x + threadIdx.x;
    unsigned thr = obits(BW2F);
    if (t < Bn * Pn) {
        u64 v = g_best[t];
        unsigned db = (unsigned)(v >> 32);
        unsigned kk = (unsigned)v;
        out[t] = (db < thr) ? (float)(kk + 1) : 0.0f;
    }
    if (t < Bn * Kn * Cn && (Bn * Pn + t) < out_size)
        out[Bn * Pn + t] = g_ms[ITERS][t];
}

extern "C" void kernel_launch(void* const* d_in, const int* in_sizes, int n_in,
                              void* d_out, int out_size) {
    const float* feat = (const float*)d_in[0];
    const void*  sidx = d_in[1];
    float* out = (float*)d_out;

    detect_idx_kernel<<<1, 256>>>(sidx);
    init_kernel<<<300, 256>>>(feat, sidx);

    dim3 grid(XB, Bn, ZS);
    for (int it = 0; it <= ITERS; it++)
        pass_kernel<<<grid, TPB>>>(feat, it);

    finalize_kernel<<<(Bn * Pn + 255) / 256, 256>>>(out, out_size);
}

// round 4
// speedup vs baseline: 1.1135x; 1.1135x over previous
#include <cuda_runtime.h>

#define Bn 4
#define Cn 16
#define Kn 100
#define Pn 76800
#define ITERS 10
#define BW2F ((float)(0.16*0.16))

#define TPB 128
#define IPT 4                    // 4 points/thread = 2 packed pairs
#define XB  (Pn/(TPB*IPT))       // 150
#define ZS  4
#define KQ  (Kn/ZS)              // 25

typedef unsigned long long u64;

// ---- device scratch (static; no allocations) ----
__device__ float g_ms[ITERS+1][Bn*Kn*Cn];
__device__ float g_num[ITERS][Bn*Kn*Cn];
__device__ float g_den[ITERS][Bn*Kn];
__device__ u64   g_best[Bn*Pn];             // packed (ordered d2 bits << 32) | k
__device__ int   g_is64;

// ---- packed f32x2 helpers ----
__device__ __forceinline__ u64 pk2(float lo, float hi) {
    u64 r; asm("mov.b64 %0,{%1,%2};" : "=l"(r) : "f"(lo), "f"(hi)); return r;
}
__device__ __forceinline__ void up2(u64 v, float& lo, float& hi) {
    asm("mov.b64 {%0,%1},%2;" : "=f"(lo), "=f"(hi) : "l"(v));
}
__device__ __forceinline__ u64 f2fma(u64 a, u64 b, u64 c) {
    u64 d; asm("fma.rn.f32x2 %0,%1,%2,%3;" : "=l"(d) : "l"(a), "l"(b), "l"(c)); return d;
}
__device__ __forceinline__ u64 f2mul(u64 a, u64 b) {
    u64 d; asm("mul.rn.f32x2 %0,%1,%2;" : "=l"(d) : "l"(a), "l"(b)); return d;
}
__device__ __forceinline__ u64 f2add(u64 a, u64 b) {
    u64 d; asm("add.rn.f32x2 %0,%1,%2;" : "=l"(d) : "l"(a), "l"(b)); return d;
}
__device__ __forceinline__ unsigned obits(float f) {
    unsigned u = __float_as_uint(f);
    return (u & 0x80000000u) ? ~u : (u | 0x80000000u);
}

// ---------------------------------------------------------------------------
__global__ void detect_idx_kernel(const void* idxraw) {
    __shared__ int bad;
    if (threadIdx.x == 0) bad = 0;
    __syncthreads();
    const long long* p = (const long long*)idxraw;
    for (int i = threadIdx.x; i < 200; i += blockDim.x) {
        long long v = p[i];
        if (v < 0 || v >= (long long)Pn) bad = 1;
    }
    __syncthreads();
    if (threadIdx.x == 0) g_is64 = bad ? 0 : 1;
}

// ---------------------------------------------------------------------------
__global__ void init_kernel(const float* __restrict__ feat,
                            const void* __restrict__ idxraw) {
    int t = blockIdx.x * blockDim.x + threadIdx.x;
    int stride = gridDim.x * blockDim.x;
    for (int i = t; i < Bn * Pn; i += stride) g_best[i] = ~0ull;
    float* num0 = &g_num[0][0];
    for (int i = t; i < ITERS * Bn * Kn * Cn; i += stride) num0[i] = 0.0f;
    float* den0 = &g_den[0][0];
    for (int i = t; i < ITERS * Bn * Kn; i += stride) den0[i] = 0.0f;

    if (t < Bn * Kn) {
        int b = t / Kn;
        long long idx;
        if (g_is64) idx = ((const long long*)idxraw)[t];
        else        idx = (long long)((const int*)idxraw)[t];
        const float* fb = feat + (size_t)b * Cn * Pn + (size_t)idx;
#pragma unroll
        for (int c = 0; c < Cn; c++)
            g_ms[0][t * Cn + c] = fb[(size_t)c * Pn];
    }
}

// drain hit-mask: one atomic burst per matched k (rare)
__device__ __forceinline__ void drain(unsigned mask, const u64* fp, int half,
                                      int b, int k0, int iter) {
    while (mask) {
        int kl = __ffs(mask) - 1;
        mask &= mask - 1;
        int kg = k0 + kl;
        atomicAdd(&g_den[iter][b * Kn + kg], 1.0f);
#pragma unroll
        for (int c = 0; c < Cn; c++) {
            float v0, v1; up2(fp[c], v0, v1);
            atomicAdd(&g_num[iter][(b * Kn + kg) * Cn + c], half ? v1 : v0);
        }
    }
}

// ---------------------------------------------------------------------------
// Per k: s = mn2 + sum f*(-2m)  (= d2 - fn2, shifted per point).
//   accumulate pass: hit iff s < bw2 - fn2  -> bitmask, drained post-loop
//   label pass:      argmin on s (order == argmin on d2); fn2 added at end
// ---------------------------------------------------------------------------
__global__ void __launch_bounds__(TPB, 5)
pass_kernel(const float* __restrict__ feat, int iter) {
    __shared__ __align__(16) u64 s_m2[KQ * Cn];   // {-2m,-2m}
    __shared__ u64 s_mn2[KQ];                     // {mn2,mn2}
    const int b = blockIdx.y;
    const int k0 = blockIdx.z * KQ;

    // ---- mean update for this k-quarter ----
    for (int kl = threadIdx.x; kl < KQ; kl += TPB) {
        int kg = k0 + kl;
        int base = (b * Kn + kg) * Cn;
        float mn2 = 0.0f;
        if (iter == 0) {
#pragma unroll
            for (int c = 0; c < Cn; c++) {
                float m = g_ms[0][base + c];
                float m2 = -2.0f * m;
                s_m2[kl * Cn + c] = pk2(m2, m2);
                mn2 += m * m;
            }
        } else {
            float den = g_den[iter - 1][b * Kn + kg];
            float dm = fmaxf(den, 1.0f);
            bool pos = den > 0.0f;
#pragma unroll
            for (int c = 0; c < Cn; c++) {
                float old = g_ms[iter - 1][base + c];
                float nm = pos ? (g_num[iter - 1][base + c] / dm) : old;
                float m2 = -2.0f * nm;
                s_m2[kl * Cn + c] = pk2(m2, m2);
                mn2 += nm * nm;
                if (blockIdx.x == 0) g_ms[iter][base + c] = nm;
            }
        }
        s_mn2[kl] = pk2(mn2, mn2);
    }
    __syncthreads();

    // ---- load 4 consecutive points (2 packed pairs) via LDG.128 ----
    const int pbase = blockIdx.x * (TPB * IPT) + 4 * threadIdx.x;
    const ulonglong2* fb2 =
        (const ulonglong2*)(feat + (size_t)b * Cn * Pn + pbase);
    u64 fpa[Cn], fpb[Cn];
    u64 fn2a = 0, fn2b = 0;
#pragma unroll
    for (int c = 0; c < Cn; c++) {
        ulonglong2 v = fb2[(size_t)c * (Pn / 4)];
        fpa[c] = v.x;
        fpb[c] = v.y;
        fn2a = c ? f2fma(v.x, v.x, fn2a) : f2mul(v.x, v.x);
        fn2b = c ? f2fma(v.y, v.y, fn2b) : f2mul(v.y, v.y);
    }
    // per-point shifted thresholds: bw2 - fn2
    float t0, t1, t2, t3;
    { float lo, hi; up2(fn2a, lo, hi); t0 = BW2F - lo; t1 = BW2F - hi; }
    { float lo, hi; up2(fn2b, lo, hi); t2 = BW2F - lo; t3 = BW2F - hi; }

    const bool lab = (iter == ITERS);
    float best0 = 3.4e38f, best1 = 3.4e38f, best2 = 3.4e38f, best3 = 3.4e38f;
    int bidx0 = 0, bidx1 = 0, bidx2 = 0, bidx3 = 0;
    unsigned mk0 = 0, mk1 = 0, mk2 = 0, mk3 = 0;

    for (int kl = 0; kl < KQ; kl++) {
        const ulonglong2* mp = (const ulonglong2*)&s_m2[kl * Cn];
        u64 mn2k = s_mn2[kl];
        // half 1: channels 0..7
        ulonglong2 m01 = mp[0], m23 = mp[1], m45 = mp[2], m67 = mp[3];
        u64 a0 = f2fma(fpa[0], m01.x, mn2k);
        u64 a1 = f2mul(fpa[1], m01.y);
        u64 a2 = f2mul(fpa[2], m23.x);
        u64 a3 = f2mul(fpa[3], m23.y);
        u64 b0 = f2fma(fpb[0], m01.x, mn2k);
        u64 b1 = f2mul(fpb[1], m01.y);
        u64 b2 = f2mul(fpb[2], m23.x);
        u64 b3 = f2mul(fpb[3], m23.y);
        a0 = f2fma(fpa[4], m45.x, a0);  b0 = f2fma(fpb[4], m45.x, b0);
        a1 = f2fma(fpa[5], m45.y, a1);  b1 = f2fma(fpb[5], m45.y, b1);
        a2 = f2fma(fpa[6], m67.x, a2);  b2 = f2fma(fpb[6], m67.x, b2);
        a3 = f2fma(fpa[7], m67.y, a3);  b3 = f2fma(fpb[7], m67.y, b3);
        // half 2: channels 8..15
        ulonglong2 m89 = mp[4], mab = mp[5], mcd = mp[6], mef = mp[7];
        a0 = f2fma(fpa[8],  m89.x, a0);  b0 = f2fma(fpb[8],  m89.x, b0);
        a1 = f2fma(fpa[9],  m89.y, a1);  b1 = f2fma(fpb[9],  m89.y, b1);
        a2 = f2fma(fpa[10], mab.x, a2);  b2 = f2fma(fpb[10], mab.x, b2);
        a3 = f2fma(fpa[11], mab.y, a3);  b3 = f2fma(fpb[11], mab.y, b3);
        a0 = f2fma(fpa[12], mcd.x, a0);  b0 = f2fma(fpb[12], mcd.x, b0);
        a1 = f2fma(fpa[13], mcd.y, a1);  b1 = f2fma(fpb[13], mcd.y, b1);
        a2 = f2fma(fpa[14], mef.x, a2);  b2 = f2fma(fpb[14], mef.x, b2);
        a3 = f2fma(fpa[15], mef.y, a3);  b3 = f2fma(fpb[15], mef.y, b3);

        u64 sa = f2add(f2add(a0, a1), f2add(a2, a3));
        u64 sb = f2add(f2add(b0, b1), f2add(b2, b3));
        float s0, s1, s2, s3;
        up2(sa, s0, s1);
        up2(sb, s2, s3);

        if (!lab) {
            mk0 |= (s0 < t0) ? (1u << kl) : 0u;
            mk1 |= (s1 < t1) ? (1u << kl) : 0u;
            mk2 |= (s2 < t2) ? (1u << kl) : 0u;
            mk3 |= (s3 < t3) ? (1u << kl) : 0u;
        } else {
            if (s0 < best0) { best0 = s0; bidx0 = k0 + kl; }
            if (s1 < best1) { best1 = s1; bidx1 = k0 + kl; }
            if (s2 < best2) { best2 = s2; bidx2 = k0 + kl; }
            if (s3 < best3) { best3 = s3; bidx3 = k0 + kl; }
        }
    }

    if (!lab) {
        if (mk0 | mk1 | mk2 | mk3) {   // rare
            drain(mk0, fpa, 0, b, k0, iter);
            drain(mk1, fpa, 1, b, k0, iter);
            drain(mk2, fpb, 0, b, k0, iter);
            drain(mk3, fpb, 1, b, k0, iter);
        }
    } else {
        float f0, f1, f2, f3;
        up2(fn2a, f0, f1);
        up2(fn2b, f2, f3);
        u64 v0 = ((u64)obits(best0 + f0) << 32) | (unsigned)bidx0;
        u64 v1 = ((u64)obits(best1 + f1) << 32) | (unsigned)bidx1;
        u64 v2 = ((u64)obits(best2 + f2) << 32) | (unsigned)bidx2;
        u64 v3 = ((u64)obits(best3 + f3) << 32) | (unsigned)bidx3;
        atomicMin(&g_best[b * Pn + pbase],     v0);
        atomicMin(&g_best[b * Pn + pbase + 1], v1);
        atomicMin(&g_best[b * Pn + pbase + 2], v2);
        atomicMin(&g_best[b * Pn + pbase + 3], v3);
    }
}

// ---------------------------------------------------------------------------
__global__ void finalize_kernel(float* __restrict__ out, int out_size) {
    int t = blockIdx.x * blockDim.x + threadIdx.x;
    unsigned thr = obits(BW2F);
    if (t < Bn * Pn) {
        u64 v = g_best[t];
        unsigned db = (unsigned)(v >> 32);
        unsigned kk = (unsigned)v;
        out[t] = (db < thr) ? (float)(kk + 1) : 0.0f;
    }
    if (t < Bn * Kn * Cn && (Bn * Pn + t) < out_size)
        out[Bn * Pn + t] = g_ms[ITERS][t];
}

extern "C" void kernel_launch(void* const* d_in, const int* in_sizes, int n_in,
                              void* d_out, int out_size) {
    const float* feat = (const float*)d_in[0];
    const void*  sidx = d_in[1];
    float* out = (float*)d_out;

    detect_idx_kernel<<<1, 256>>>(sidx);
    init_kernel<<<300, 256>>>(feat, sidx);

    dim3 grid(XB, Bn, ZS);
    for (int it = 0; it <= ITERS; it++)
        pass_kernel<<<grid, TPB>>>(feat, it);

    finalize_kernel<<<(Bn * Pn + 255) / 256, 256>>>(out, out_size);
}

// round 5
// speedup vs baseline: 1.1386x; 1.0225x over previous
#include <cuda_runtime.h>

#define Bn 4
#define Cn 16
#define Kn 100
#define Pn 76800
#define ITERS 10
#define BW2F ((float)(0.16*0.16))

#define TPB 128
#define IPT 4                    // 4 points/thread
#define XB  (Pn/(TPB*IPT))       // 150
#define ZS  4
#define KQ  (Kn/ZS)              // 25
#define MSTR 20                  // smem floats per k: 16 ch + mn2 + 0 + pad

typedef unsigned long long u64;

// ---- device scratch (static; no allocations) ----
__device__ float g_ms[ITERS+1][Bn*Kn*Cn];
__device__ float g_num[ITERS][Bn*Kn*Cn];
__device__ float g_den[ITERS][Bn*Kn];
__device__ u64   g_best[Bn*Pn];
__device__ int   g_is64;

// ---- packed f32x2 helpers ----
__device__ __forceinline__ u64 pk2(float lo, float hi) {
    u64 r; asm("mov.b64 %0,{%1,%2};" : "=l"(r) : "f"(lo), "f"(hi)); return r;
}
__device__ __forceinline__ void up2(u64 v, float& lo, float& hi) {
    asm("mov.b64 {%0,%1},%2;" : "=f"(lo), "=f"(hi) : "l"(v));
}
__device__ __forceinline__ u64 f2fma(u64 a, u64 b, u64 c) {
    u64 d; asm("fma.rn.f32x2 %0,%1,%2,%3;" : "=l"(d) : "l"(a), "l"(b), "l"(c)); return d;
}
__device__ __forceinline__ u64 f2mul(u64 a, u64 b) {
    u64 d; asm("mul.rn.f32x2 %0,%1,%2;" : "=l"(d) : "l"(a), "l"(b)); return d;
}
__device__ __forceinline__ unsigned obits(float f) {
    unsigned u = __float_as_uint(f);
    return (u & 0x80000000u) ? ~u : (u | 0x80000000u);
}

// ---------------------------------------------------------------------------
__global__ void detect_idx_kernel(const void* idxraw) {
    __shared__ int bad;
    if (threadIdx.x == 0) bad = 0;
    __syncthreads();
    const long long* p = (const long long*)idxraw;
    for (int i = threadIdx.x; i < 200; i += blockDim.x) {
        long long v = p[i];
        if (v < 0 || v >= (long long)Pn) bad = 1;
    }
    __syncthreads();
    if (threadIdx.x == 0) g_is64 = bad ? 0 : 1;
}

// ---------------------------------------------------------------------------
__global__ void init_kernel(const float* __restrict__ feat,
                            const void* __restrict__ idxraw) {
    int t = blockIdx.x * blockDim.x + threadIdx.x;
    int stride = gridDim.x * blockDim.x;
    for (int i = t; i < Bn * Pn; i += stride) g_best[i] = ~0ull;
    float* num0 = &g_num[0][0];
    for (int i = t; i < ITERS * Bn * Kn * Cn; i += stride) num0[i] = 0.0f;
    float* den0 = &g_den[0][0];
    for (int i = t; i < ITERS * Bn * Kn; i += stride) den0[i] = 0.0f;

    if (t < Bn * Kn) {
        int b = t / Kn;
        long long idx;
        if (g_is64) idx = ((const long long*)idxraw)[t];
        else        idx = (long long)((const int*)idxraw)[t];
        const float* fb = feat + (size_t)b * Cn * Pn + (size_t)idx;
#pragma unroll
        for (int c = 0; c < Cn; c++)
            g_ms[0][t * Cn + c] = fb[(size_t)c * Pn];
    }
}

// shifted distance for one point vs one k: s = mn2 + sum_c f_c * (-2 m_c)
__device__ __forceinline__ u64 dchain(const u64 (&f)[8], const float* mk) {
    const ulonglong2* mp = (const ulonglong2*)mk;
    u64 mnz = *(const u64*)(mk + 16);     // {mn2, 0}
    ulonglong2 mA = mp[0], mB = mp[1], mC = mp[2], mD = mp[3];
    u64 a = f2fma(f[0], mA.x, mnz);
    u64 b = f2mul(f[1], mA.y);
    a = f2fma(f[2], mB.x, a);
    b = f2fma(f[3], mB.y, b);
    a = f2fma(f[4], mC.x, a);
    b = f2fma(f[5], mC.y, b);
    a = f2fma(f[6], mD.x, a);
    b = f2fma(f[7], mD.y, b);
    // combine the two partial chains; lane-sum done by caller
    float alo, ahi, blo, bhi;
    up2(a, alo, ahi); up2(b, blo, bhi);
    return pk2(alo + blo, ahi + bhi);
}

// rare slow path: rescan all KQ means for one point, do exact hit atomics
__device__ __noinline__ void rescan(const u64 (&f)[8], float thr,
                                    const float* s_m, int b, int k0, int iter) {
    for (int kl = 0; kl < KQ; kl++) {
        u64 s2 = dchain(f, &s_m[kl * MSTR]);
        float lo, hi; up2(s2, lo, hi);
        if (lo + hi < thr) {
            int kg = k0 + kl;
            atomicAdd(&g_den[iter][b * Kn + kg], 1.0f);
#pragma unroll
            for (int j = 0; j < 8; j++) {
                float v0, v1; up2(f[j], v0, v1);
                atomicAdd(&g_num[iter][(b * Kn + kg) * Cn + 2 * j],     v0);
                atomicAdd(&g_num[iter][(b * Kn + kg) * Cn + 2 * j + 1], v1);
            }
        }
    }
}

// ---------------------------------------------------------------------------
// Channel-packed f32x2. smem means: [KQ][20] floats = {-2m x16, mn2, 0, pad}.
// Hot loop per (warp,k): 4 LDS.128 + 1 LDS.64, 32 f2fma + 4 FADD + 4 FMNMX.
// accumulate pass: running min per point -> rare rescan for hits.
// label pass (iter==ITERS): argmin + atomicMin of packed (d2bits|k).
// ---------------------------------------------------------------------------
__global__ void __launch_bounds__(TPB, 5)
pass_kernel(const float* __restrict__ feat, int iter) {
    __shared__ __align__(16) float s_m[KQ * MSTR];
    const int b = blockIdx.y;
    const int k0 = blockIdx.z * KQ;

    // ---- mean update for this k-quarter ----
    for (int kl = threadIdx.x; kl < KQ; kl += TPB) {
        int kg = k0 + kl;
        int base = (b * Kn + kg) * Cn;
        float mn2 = 0.0f;
        if (iter == 0) {
#pragma unroll
            for (int c = 0; c < Cn; c++) {
                float m = g_ms[0][base + c];
                s_m[kl * MSTR + c] = -2.0f * m;
                mn2 += m * m;
            }
        } else {
            float den = g_den[iter - 1][b * Kn + kg];
            float dm = fmaxf(den, 1.0f);
            bool pos = den > 0.0f;
#pragma unroll
            for (int c = 0; c < Cn; c++) {
                float old = g_ms[iter - 1][base + c];
                float nm = pos ? (g_num[iter - 1][base + c] / dm) : old;
                s_m[kl * MSTR + c] = -2.0f * nm;
                mn2 += nm * nm;
                if (blockIdx.x == 0) g_ms[iter][base + c] = nm;
            }
        }
        s_m[kl * MSTR + 16] = mn2;
        s_m[kl * MSTR + 17] = 0.0f;
    }
    __syncthreads();

    // ---- load 4 consecutive points; transpose to channel-packed pairs ----
    const int pbase = blockIdx.x * (TPB * IPT) + 4 * threadIdx.x;
    const float4* fb4 = (const float4*)(feat + (size_t)b * Cn * Pn + pbase);
    u64 f0[8], f1[8], f2[8], f3[8];
#pragma unroll
    for (int c = 0; c < Cn; c += 2) {
        float4 va = fb4[(size_t)c * (Pn / 4)];
        float4 vb = fb4[(size_t)(c + 1) * (Pn / 4)];
        f0[c / 2] = pk2(va.x, vb.x);
        f1[c / 2] = pk2(va.y, vb.y);
        f2[c / 2] = pk2(va.z, vb.z);
        f3[c / 2] = pk2(va.w, vb.w);
    }
    float fn2_0 = 0, fn2_1 = 0, fn2_2 = 0, fn2_3 = 0;
    {
        u64 q0 = f2mul(f0[0], f0[0]), q1 = f2mul(f1[0], f1[0]);
        u64 q2 = f2mul(f2[0], f2[0]), q3 = f2mul(f3[0], f3[0]);
#pragma unroll
        for (int j = 1; j < 8; j++) {
            q0 = f2fma(f0[j], f0[j], q0);
            q1 = f2fma(f1[j], f1[j], q1);
            q2 = f2fma(f2[j], f2[j], q2);
            q3 = f2fma(f3[j], f3[j], q3);
        }
        float lo, hi;
        up2(q0, lo, hi); fn2_0 = lo + hi;
        up2(q1, lo, hi); fn2_1 = lo + hi;
        up2(q2, lo, hi); fn2_2 = lo + hi;
        up2(q3, lo, hi); fn2_3 = lo + hi;
    }
    const float t0 = BW2F - fn2_0, t1 = BW2F - fn2_1;
    const float t2 = BW2F - fn2_2, t3 = BW2F - fn2_3;

    const bool lab = (iter == ITERS);
    float s0m = 3.4e38f, s1m = 3.4e38f, s2m = 3.4e38f, s3m = 3.4e38f;
    int i0 = 0, i1 = 0, i2 = 0, i3 = 0;

#pragma unroll 5
    for (int kl = 0; kl < KQ; kl++) {
        const float* mk = &s_m[kl * MSTR];
        u64 p0 = dchain(f0, mk);
        u64 p1 = dchain(f1, mk);
        u64 p2 = dchain(f2, mk);
        u64 p3 = dchain(f3, mk);
        float lo, hi, s0, s1, s2, s3;
        up2(p0, lo, hi); s0 = lo + hi;
        up2(p1, lo, hi); s1 = lo + hi;
        up2(p2, lo, hi); s2 = lo + hi;
        up2(p3, lo, hi); s3 = lo + hi;
        if (!lab) {
            s0m = fminf(s0m, s0);
            s1m = fminf(s1m, s1);
            s2m = fminf(s2m, s2);
            s3m = fminf(s3m, s3);
        } else {
            if (s0 < s0m) { s0m = s0; i0 = k0 + kl; }
            if (s1 < s1m) { s1m = s1; i1 = k0 + kl; }
            if (s2 < s2m) { s2m = s2; i2 = k0 + kl; }
            if (s3 < s3m) { s3m = s3; i3 = k0 + kl; }
        }
    }

    if (!lab) {
        // hits are rare (typically only seed pixels)
        if (s0m < t0) rescan(f0, t0, s_m, b, k0, iter);
        if (s1m < t1) rescan(f1, t1, s_m, b, k0, iter);
        if (s2m < t2) rescan(f2, t2, s_m, b, k0, iter);
        if (s3m < t3) rescan(f3, t3, s_m, b, k0, iter);
    } else {
        u64 v0 = ((u64)obits(s0m + fn2_0) << 32) | (unsigned)i0;
        u64 v1 = ((u64)obits(s1m + fn2_1) << 32) | (unsigned)i1;
        u64 v2 = ((u64)obits(s2m + fn2_2) << 32) | (unsigned)i2;
        u64 v3 = ((u64)obits(s3m + fn2_3) << 32) | (unsigned)i3;
        atomicMin(&g_best[b * Pn + pbase],     v0);
        atomicMin(&g_best[b * Pn + pbase + 1], v1);
        atomicMin(&g_best[b * Pn + pbase + 2], v2);
        atomicMin(&g_best[b * Pn + pbase + 3], v3);
    }
}

// ---------------------------------------------------------------------------
__global__ void finalize_kernel(float* __restrict__ out, int out_size) {
    int t = blockIdx.x * blockDim.x + threadIdx.x;
    unsigned thr = obits(BW2F);
    if (t < Bn * Pn) {
        u64 v = g_best[t];
        unsigned db = (unsigned)(v >> 32);
        unsigned kk = (unsigned)v;
        out[t] = (db < thr) ? (float)(kk + 1) : 0.0f;
    }
    if (t < Bn * Kn * Cn && (Bn * Pn + t) < out_size)
        out[Bn * Pn + t] = g_ms[ITERS][t];
}

extern "C" void kernel_launch(void* const* d_in, const int* in_sizes, int n_in,
                              void* d_out, int out_size) {
    const float* feat = (const float*)d_in[0];
    const void*  sidx = d_in[1];
    float* out = (float*)d_out;

    detect_idx_kernel<<<1, 256>>>(sidx);
    init_kernel<<<300, 256>>>(feat, sidx);

    dim3 grid(XB, Bn, ZS);
    for (int it = 0; it <= ITERS; it++)
        pass_kernel<<<grid, TPB>>>(feat, it);

    finalize_kernel<<<(Bn * Pn + 255) / 256, 256>>>(out, out_size);
}

// round 6
// speedup vs baseline: 1.2756x; 1.1204x over previous
#include <cuda_runtime.h>

#define Bn 4
#define Cn 16
#define Kn 100
#define Pn 76800
#define ITERS 10
#define BW2F ((float)(0.16*0.16))

#define TPB 128
#define IPT 4                    // 4 points/thread
#define XB  (Pn/(TPB*IPT))       // 150
#define ZS  4
#define KQ  (Kn/ZS)              // 25
#define MSTR 20                  // floats per k: 16 ch + mn2 + 0 + pad (16B-aligned rows)

typedef unsigned long long u64;

// ---- device scratch (static; no allocations) ----
__device__ float g_ms[ITERS+1][Bn*Kn*Cn];
__device__ float g_num[ITERS][Bn*Kn*Cn];
__device__ float g_den[ITERS][Bn*Kn];
__device__ u64   g_best[Bn*Pn];
__device__ int   g_is64;

// ---- packed f32x2 helpers ----
__device__ __forceinline__ u64 pk2(float lo, float hi) {
    u64 r; asm("mov.b64 %0,{%1,%2};" : "=l"(r) : "f"(lo), "f"(hi)); return r;
}
__device__ __forceinline__ void up2(u64 v, float& lo, float& hi) {
    asm("mov.b64 {%0,%1},%2;" : "=f"(lo), "=f"(hi) : "l"(v));
}
__device__ __forceinline__ u64 f2fma(u64 a, u64 b, u64 c) {
    u64 d; asm("fma.rn.f32x2 %0,%1,%2,%3;" : "=l"(d) : "l"(a), "l"(b), "l"(c)); return d;
}
__device__ __forceinline__ u64 f2mul(u64 a, u64 b) {
    u64 d; asm("mul.rn.f32x2 %0,%1,%2;" : "=l"(d) : "l"(a), "l"(b)); return d;
}
__device__ __forceinline__ unsigned obits(float f) {
    unsigned u = __float_as_uint(f);
    return (u & 0x80000000u) ? ~u : (u | 0x80000000u);
}

// ---------------------------------------------------------------------------
__global__ void detect_idx_kernel(const void* idxraw) {
    __shared__ int bad;
    if (threadIdx.x == 0) bad = 0;
    __syncthreads();
    const long long* p = (const long long*)idxraw;
    for (int i = threadIdx.x; i < 200; i += blockDim.x) {
        long long v = p[i];
        if (v < 0 || v >= (long long)Pn) bad = 1;
    }
    __syncthreads();
    if (threadIdx.x == 0) g_is64 = bad ? 0 : 1;
}

// ---------------------------------------------------------------------------
__global__ void init_kernel(const float* __restrict__ feat,
                            const void* __restrict__ idxraw) {
    int t = blockIdx.x * blockDim.x + threadIdx.x;
    int stride = gridDim.x * blockDim.x;
    for (int i = t; i < Bn * Pn; i += stride) g_best[i] = ~0ull;
    float* num0 = &g_num[0][0];
    for (int i = t; i < ITERS * Bn * Kn * Cn; i += stride) num0[i] = 0.0f;
    float* den0 = &g_den[0][0];
    for (int i = t; i < ITERS * Bn * Kn; i += stride) den0[i] = 0.0f;

    if (t < Bn * Kn) {
        int b = t / Kn;
        long long idx;
        if (g_is64) idx = ((const long long*)idxraw)[t];
        else        idx = (long long)((const int*)idxraw)[t];
        const float* fb = feat + (size_t)b * Cn * Pn + (size_t)idx;
#pragma unroll
        for (int c = 0; c < Cn; c++)
            g_ms[0][t * Cn + c] = fb[(size_t)c * Pn];
    }
}

// single-chain shifted distance: s = mn2 + sum_c f_c * (-2 m_c)
__device__ __forceinline__ float dchain1(const u64 (&f)[8],
                                         ulonglong2 mA, ulonglong2 mB,
                                         ulonglong2 mC, ulonglong2 mD,
                                         u64 mnz) {
    u64 v = f2fma(f[0], mA.x, mnz);
    v = f2fma(f[1], mA.y, v);
    v = f2fma(f[2], mB.x, v);
    v = f2fma(f[3], mB.y, v);
    v = f2fma(f[4], mC.x, v);
    v = f2fma(f[5], mC.y, v);
    v = f2fma(f[6], mD.x, v);
    v = f2fma(f[7], mD.y, v);
    float lo, hi; up2(v, lo, hi);
    return lo + hi;
}

// rare slow path: rescan all KQ means for one point, do exact hit atomics
__device__ __noinline__ void rescan(const u64 (&f)[8], float thr,
                                    const float* s_m, int b, int k0, int iter) {
    for (int kl = 0; kl < KQ; kl++) {
        const ulonglong2* mp = (const ulonglong2*)&s_m[kl * MSTR];
        u64 mnz = *(const u64*)&s_m[kl * MSTR + 16];
        float s = dchain1(f, mp[0], mp[1], mp[2], mp[3], mnz);
        if (s < thr) {
            int kg = k0 + kl;
            atomicAdd(&g_den[iter][b * Kn + kg], 1.0f);
#pragma unroll
            for (int j = 0; j < 8; j++) {
                float v0, v1; up2(f[j], v0, v1);
                atomicAdd(&g_num[iter][(b * Kn + kg) * Cn + 2 * j],     v0);
                atomicAdd(&g_num[iter][(b * Kn + kg) * Cn + 2 * j + 1], v1);
            }
        }
    }
}

// ---------------------------------------------------------------------------
// Channel-packed f32x2, one 8-deep fma chain per point per k.
// smem means: [KQ][20] floats = {-2m x16, mn2, 0, pad2}.
// Hot loop per (warp,k): 4 LDS.128 + 1 LDS.64, 32 f2fma + 4 FADD + 4 FMNMX.
// ---------------------------------------------------------------------------
__global__ void __launch_bounds__(TPB, 5)
pass_kernel(const float* __restrict__ feat, int iter) {
    __shared__ __align__(16) float s_m[KQ * MSTR];
    const int b = blockIdx.y;
    const int k0 = blockIdx.z * KQ;

    // ---- mean update for this k-quarter ----
    for (int kl = threadIdx.x; kl < KQ; kl += TPB) {
        int kg = k0 + kl;
        int base = (b * Kn + kg) * Cn;
        float mn2 = 0.0f;
        if (iter == 0) {
#pragma unroll
            for (int c = 0; c < Cn; c++) {
                float m = g_ms[0][base + c];
                s_m[kl * MSTR + c] = -2.0f * m;
                mn2 += m * m;
            }
        } else {
            float den = g_den[iter - 1][b * Kn + kg];
            float dm = fmaxf(den, 1.0f);
            bool pos = den > 0.0f;
#pragma unroll
            for (int c = 0; c < Cn; c++) {
                float old = g_ms[iter - 1][base + c];
                float nm = pos ? (g_num[iter - 1][base + c] / dm) : old;
                s_m[kl * MSTR + c] = -2.0f * nm;
                mn2 += nm * nm;
                if (blockIdx.x == 0) g_ms[iter][base + c] = nm;
            }
        }
        s_m[kl * MSTR + 16] = mn2;
        s_m[kl * MSTR + 17] = 0.0f;
    }
    __syncthreads();

    // ---- load 4 consecutive points; transpose to channel-packed pairs ----
    const int pbase = blockIdx.x * (TPB * IPT) + 4 * threadIdx.x;
    const float4* fb4 = (const float4*)(feat + (size_t)b * Cn * Pn + pbase);
    u64 f0[8], f1[8], f2[8], f3[8];
#pragma unroll
    for (int c = 0; c < Cn; c += 2) {
        float4 va = fb4[(size_t)c * (Pn / 4)];
        float4 vb = fb4[(size_t)(c + 1) * (Pn / 4)];
        f0[c / 2] = pk2(va.x, vb.x);
        f1[c / 2] = pk2(va.y, vb.y);
        f2[c / 2] = pk2(va.z, vb.z);
        f3[c / 2] = pk2(va.w, vb.w);
    }
    float fn2_0, fn2_1, fn2_2, fn2_3;
    {
        u64 q0 = f2mul(f0[0], f0[0]), q1 = f2mul(f1[0], f1[0]);
        u64 q2 = f2mul(f2[0], f2[0]), q3 = f2mul(f3[0], f3[0]);
#pragma unroll
        for (int j = 1; j < 8; j++) {
            q0 = f2fma(f0[j], f0[j], q0);
            q1 = f2fma(f1[j], f1[j], q1);
            q2 = f2fma(f2[j], f2[j], q2);
            q3 = f2fma(f3[j], f3[j], q3);
        }
        float lo, hi;
        up2(q0, lo, hi); fn2_0 = lo + hi;
        up2(q1, lo, hi); fn2_1 = lo + hi;
        up2(q2, lo, hi); fn2_2 = lo + hi;
        up2(q3, lo, hi); fn2_3 = lo + hi;
    }
    const float t0 = BW2F - fn2_0, t1 = BW2F - fn2_1;
    const float t2 = BW2F - fn2_2, t3 = BW2F - fn2_3;

    const bool lab = (iter == ITERS);
    float s0m = 3.4e38f, s1m = 3.4e38f, s2m = 3.4e38f, s3m = 3.4e38f;
    int i0 = 0, i1 = 0, i2 = 0, i3 = 0;

#pragma unroll 5
    for (int kl = 0; kl < KQ; kl++) {
        const ulonglong2* mp = (const ulonglong2*)&s_m[kl * MSTR];
        ulonglong2 mA = mp[0], mB = mp[1], mC = mp[2], mD = mp[3];
        u64 mnz = *(const u64*)&s_m[kl * MSTR + 16];
        float s0 = dchain1(f0, mA, mB, mC, mD, mnz);
        float s1 = dchain1(f1, mA, mB, mC, mD, mnz);
        float s2 = dchain1(f2, mA, mB, mC, mD, mnz);
        float s3 = dchain1(f3, mA, mB, mC, mD, mnz);
        if (!lab) {
            s0m = fminf(s0m, s0);
            s1m = fminf(s1m, s1);
            s2m = fminf(s2m, s2);
            s3m = fminf(s3m, s3);
        } else {
            if (s0 < s0m) { s0m = s0; i0 = k0 + kl; }
            if (s1 < s1m) { s1m = s1; i1 = k0 + kl; }
            if (s2 < s2m) { s2m = s2; i2 = k0 + kl; }
            if (s3 < s3m) { s3m = s3; i3 = k0 + kl; }
        }
    }

    if (!lab) {
        if (s0m < t0) rescan(f0, t0, s_m, b, k0, iter);
        if (s1m < t1) rescan(f1, t1, s_m, b, k0, iter);
        if (s2m < t2) rescan(f2, t2, s_m, b, k0, iter);
        if (s3m < t3) rescan(f3, t3, s_m, b, k0, iter);
    } else {
        u64 v0 = ((u64)obits(s0m + fn2_0) << 32) | (unsigned)i0;
        u64 v1 = ((u64)obits(s1m + fn2_1) << 32) | (unsigned)i1;
        u64 v2 = ((u64)obits(s2m + fn2_2) << 32) | (unsigned)i2;
        u64 v3 = ((u64)obits(s3m + fn2_3) << 32) | (unsigned)i3;
        atomicMin(&g_best[b * Pn + pbase],     v0);
        atomicMin(&g_best[b * Pn + pbase + 1], v1);
        atomicMin(&g_best[b * Pn + pbase + 2], v2);
        atomicMin(&g_best[b * Pn + pbase + 3], v3);
    }
}

// ---------------------------------------------------------------------------
__global__ void finalize_kernel(float* __restrict__ out, int out_size) {
    int t = blockIdx.x * blockDim.x + threadIdx.x;
    unsigned thr = obits(BW2F);
    if (t < Bn * Pn) {
        u64 v = g_best[t];
        unsigned db = (unsigned)(v >> 32);
        unsigned kk = (unsigned)v;
        out[t] = (db < thr) ? (float)(kk + 1) : 0.0f;
    }
    if (t < Bn * Kn * Cn && (Bn * Pn + t) < out_size)
        out[Bn * Pn + t] = g_ms[ITERS][t];
}

extern "C" void kernel_launch(void* const* d_in, const int* in_sizes, int n_in,
                              void* d_out, int out_size) {
    const float* feat = (const float*)d_in[0];
    const void*  sidx = d_in[1];
    float* out = (float*)d_out;

    detect_idx_kernel<<<1, 256>>>(sidx);
    init_kernel<<<300, 256>>>(feat, sidx);

    dim3 grid(XB, Bn, ZS);
    for (int it = 0; it <= ITERS; it++)
        pass_kernel<<<grid, TPB>>>(feat, it);

    finalize_kernel<<<(Bn * Pn + 255) / 256, 256>>>(out, out_size);
}

// round 7
// speedup vs baseline: 2.8997x; 2.2732x over previous
#include <cuda_runtime.h>

#define Bn 4
#define Cn 16
#define Kn 100
#define Pn 76800
#define ITERS 10
#define BW2F ((float)(0.16*0.16))

#define TPB 128
#define IPT 4                    // 4 points/thread
#define XB  (Pn/(TPB*IPT))       // 150
#define ZS  4
#define KQ  (Kn/ZS)              // 25
#define MSTR 20                  // floats per k: {-2m x16, mn2, 0, pad2}

typedef unsigned long long u64;

// ---- device scratch (static; no allocations) ----
__device__ float g_ms[ITERS+1][Bn*Kn*Cn];        // means entering iter t
__device__ float g_prep[ITERS+1][Bn*Kn*MSTR];    // {-2m, mn2} tables
__device__ float g_num[ITERS][Bn*Kn*Cn];
__device__ float g_den[ITERS][Bn*Kn];
__device__ u64   g_best[Bn*Pn];
__device__ int   g_is64;
__device__ int   g_conv;                          // latched fixed-point flag

// ---- packed f32x2 helpers ----
__device__ __forceinline__ u64 pk2(float lo, float hi) {
    u64 r; asm("mov.b64 %0,{%1,%2};" : "=l"(r) : "f"(lo), "f"(hi)); return r;
}
__device__ __forceinline__ void up2(u64 v, float& lo, float& hi) {
    asm("mov.b64 {%0,%1},%2;" : "=f"(lo), "=f"(hi) : "l"(v));
}
__device__ __forceinline__ u64 f2fma(u64 a, u64 b, u64 c) {
    u64 d; asm("fma.rn.f32x2 %0,%1,%2,%3;" : "=l"(d) : "l"(a), "l"(b), "l"(c)); return d;
}
__device__ __forceinline__ u64 f2mul(u64 a, u64 b) {
    u64 d; asm("mul.rn.f32x2 %0,%1,%2;" : "=l"(d) : "l"(a), "l"(b)); return d;
}
__device__ __forceinline__ unsigned obits(float f) {
    unsigned u = __float_as_uint(f);
    return (u & 0x80000000u) ? ~u : (u | 0x80000000u);
}

// ---------------------------------------------------------------------------
__global__ void detect_idx_kernel(const void* idxraw) {
    __shared__ int bad;
    if (threadIdx.x == 0) bad = 0;
    __syncthreads();
    const long long* p = (const long long*)idxraw;
    for (int i = threadIdx.x; i < 200; i += blockDim.x) {
        long long v = p[i];
        if (v < 0 || v >= (long long)Pn) bad = 1;
    }
    __syncthreads();
    if (threadIdx.x == 0) g_is64 = bad ? 0 : 1;
}

// ---------------------------------------------------------------------------
// Zero accumulators + conv flag, gather seed means, build prep[0].
// ---------------------------------------------------------------------------
__global__ void init_kernel(const float* __restrict__ feat,
                            const void* __restrict__ idxraw) {
    int t = blockIdx.x * blockDim.x + threadIdx.x;
    int stride = gridDim.x * blockDim.x;
    if (t == 0) g_conv = 0;
    for (int i = t; i < Bn * Pn; i += stride) g_best[i] = ~0ull;
    float* num0 = &g_num[0][0];
    for (int i = t; i < ITERS * Bn * Kn * Cn; i += stride) num0[i] = 0.0f;
    float* den0 = &g_den[0][0];
    for (int i = t; i < ITERS * Bn * Kn; i += stride) den0[i] = 0.0f;

    if (t < Bn * Kn) {
        int b = t / Kn;
        long long idx;
        if (g_is64) idx = ((const long long*)idxraw)[t];
        else        idx = (long long)((const int*)idxraw)[t];
        const float* fb = feat + (size_t)b * Cn * Pn + (size_t)idx;
        float mn2 = 0.0f;
#pragma unroll
        for (int c = 0; c < Cn; c++) {
            float m = fb[(size_t)c * Pn];
            g_ms[0][t * Cn + c] = m;
            g_prep[0][t * MSTR + c] = -2.0f * m;
            mn2 += m * m;
        }
        g_prep[0][t * MSTR + 16] = mn2;
        g_prep[0][t * MSTR + 17] = 0.0f;
    }
}

// ---------------------------------------------------------------------------
// Single-block update: means[it+1] from num/den[it]; prep[it+1]; latch g_conv
// when means[it+1] == means[it] bitwise for ALL clusters.
// ---------------------------------------------------------------------------
__global__ void update_kernel(int it) {
    __shared__ int s_same;
    int t = threadIdx.x;
    if (t == 0) s_same = 1;
    __syncthreads();
    if (t < Bn * Kn) {
        float den = g_den[it][t];
        float dm = fmaxf(den, 1.0f);
        bool pos = den > 0.0f;
        bool same = true;
        float mn2 = 0.0f;
#pragma unroll
        for (int c = 0; c < Cn; c++) {
            float old = g_ms[it][t * Cn + c];
            float nm = pos ? (g_num[it][t * Cn + c] / dm) : old;
            g_ms[it + 1][t * Cn + c] = nm;
            g_prep[it + 1][t * MSTR + c] = -2.0f * nm;
            mn2 += nm * nm;
            same = same && (__float_as_uint(nm) == __float_as_uint(old));
        }
        g_prep[it + 1][t * MSTR + 16] = mn2;
        g_prep[it + 1][t * MSTR + 17] = 0.0f;
        if (!same) s_same = 0;
    }
    __syncthreads();
    if (t == 0 && s_same) g_conv = 1;
}

// single-chain shifted distance: s = mn2 + sum_c f_c * (-2 m_c)
__device__ __forceinline__ float dchain1(const u64 (&f)[8],
                                         ulonglong2 mA, ulonglong2 mB,
                                         ulonglong2 mC, ulonglong2 mD,
                                         u64 mnz) {
    u64 v = f2fma(f[0], mA.x, mnz);
    v = f2fma(f[1], mA.y, v);
    v = f2fma(f[2], mB.x, v);
    v = f2fma(f[3], mB.y, v);
    v = f2fma(f[4], mC.x, v);
    v = f2fma(f[5], mC.y, v);
    v = f2fma(f[6], mD.x, v);
    v = f2fma(f[7], mD.y, v);
    float lo, hi; up2(v, lo, hi);
    return lo + hi;
}

// rare slow path: rescan all KQ means for one point, exact hit atomics
__device__ __noinline__ void rescan(const u64 (&f)[8], float thr,
                                    const float* s_m, int b, int k0, int iter) {
    for (int kl = 0; kl < KQ; kl++) {
        const ulonglong2* mp = (const ulonglong2*)&s_m[kl * MSTR];
        u64 mnz = *(const u64*)&s_m[kl * MSTR + 16];
        float s = dchain1(f, mp[0], mp[1], mp[2], mp[3], mnz);
        if (s < thr) {
            int kg = k0 + kl;
            atomicAdd(&g_den[iter][b * Kn + kg], 1.0f);
#pragma unroll
            for (int j = 0; j < 8; j++) {
                float v0, v1; up2(f[j], v0, v1);
                atomicAdd(&g_num[iter][(b * Kn + kg) * Cn + 2 * j],     v0);
                atomicAdd(&g_num[iter][(b * Kn + kg) * Cn + 2 * j + 1], v1);
            }
        }
    }
}

// ---------------------------------------------------------------------------
// Scan pass. iter<ITERS: accumulate (skipped once converged). iter==ITERS:
// label pass (always runs). Means read pre-transformed from g_prep[iter].
// ---------------------------------------------------------------------------
__global__ void __launch_bounds__(TPB, 5)
scan_kernel(const float* __restrict__ feat, int iter) {
    if (iter > 0 && iter < ITERS && g_conv) return;   // fixed point reached

    __shared__ __align__(16) float s_m[KQ * MSTR];
    const int b = blockIdx.y;
    const int k0 = blockIdx.z * KQ;

    // copy this quarter's prep table (contiguous, 125 float4)
    {
        const float4* src =
            (const float4*)&g_prep[iter][(b * Kn + k0) * MSTR];
        float4* dst = (float4*)s_m;
        for (int i = threadIdx.x; i < KQ * MSTR / 4; i += TPB)
            dst[i] = src[i];
    }
    __syncthreads();

    // ---- load 4 consecutive points; transpose to channel-packed pairs ----
    const int pbase = blockIdx.x * (TPB * IPT) + 4 * threadIdx.x;
    const float4* fb4 = (const float4*)(feat + (size_t)b * Cn * Pn + pbase);
    u64 f0[8], f1[8], f2[8], f3[8];
#pragma unroll
    for (int c = 0; c < Cn; c += 2) {
        float4 va = fb4[(size_t)c * (Pn / 4)];
        float4 vb = fb4[(size_t)(c + 1) * (Pn / 4)];
        f0[c / 2] = pk2(va.x, vb.x);
        f1[c / 2] = pk2(va.y, vb.y);
        f2[c / 2] = pk2(va.z, vb.z);
        f3[c / 2] = pk2(va.w, vb.w);
    }
    float fn2_0, fn2_1, fn2_2, fn2_3;
    {
        u64 q0 = f2mul(f0[0], f0[0]), q1 = f2mul(f1[0], f1[0]);
        u64 q2 = f2mul(f2[0], f2[0]), q3 = f2mul(f3[0], f3[0]);
#pragma unroll
        for (int j = 1; j < 8; j++) {
            q0 = f2fma(f0[j], f0[j], q0);
            q1 = f2fma(f1[j], f1[j], q1);
            q2 = f2fma(f2[j], f2[j], q2);
            q3 = f2fma(f3[j], f3[j], q3);
        }
        float lo, hi;
        up2(q0, lo, hi); fn2_0 = lo + hi;
        up2(q1, lo, hi); fn2_1 = lo + hi;
        up2(q2, lo, hi); fn2_2 = lo + hi;
        up2(q3, lo, hi); fn2_3 = lo + hi;
    }
    const float t0 = BW2F - fn2_0, t1 = BW2F - fn2_1;
    const float t2 = BW2F - fn2_2, t3 = BW2F - fn2_3;

    const bool lab = (iter == ITERS);
    float s0m = 3.4e38f, s1m = 3.4e38f, s2m = 3.4e38f, s3m = 3.4e38f;
    int i0 = 0, i1 = 0, i2 = 0, i3 = 0;

#pragma unroll 5
    for (int kl = 0; kl < KQ; kl++) {
        const ulonglong2* mp = (const ulonglong2*)&s_m[kl * MSTR];
        ulonglong2 mA = mp[0], mB = mp[1], mC = mp[2], mD = mp[3];
        u64 mnz = *(const u64*)&s_m[kl * MSTR + 16];
        float s0 = dchain1(f0, mA, mB, mC, mD, mnz);
        float s1 = dchain1(f1, mA, mB, mC, mD, mnz);
        float s2 = dchain1(f2, mA, mB, mC, mD, mnz);
        float s3 = dchain1(f3, mA, mB, mC, mD, mnz);
        if (!lab) {
            s0m = fminf(s0m, s0);
            s1m = fminf(s1m, s1);
            s2m = fminf(s2m, s2);
            s3m = fminf(s3m, s3);
        } else {
            if (s0 < s0m) { s0m = s0; i0 = k0 + kl; }
            if (s1 < s1m) { s1m = s1; i1 = k0 + kl; }
            if (s2 < s2m) { s2m = s2; i2 = k0 + kl; }
            if (s3 < s3m) { s3m = s3; i3 = k0 + kl; }
        }
    }

    if (!lab) {
        if (s0m < t0) rescan(f0, t0, s_m, b, k0, iter);
        if (s1m < t1) rescan(f1, t1, s_m, b, k0, iter);
        if (s2m < t2) rescan(f2, t2, s_m, b, k0, iter);
        if (s3m < t3) rescan(f3, t3, s_m, b, k0, iter);
    } else {
        u64 v0 = ((u64)obits(s0m + fn2_0) << 32) | (unsigned)i0;
        u64 v1 = ((u64)obits(s1m + fn2_1) << 32) | (unsigned)i1;
        u64 v2 = ((u64)obits(s2m + fn2_2) << 32) | (unsigned)i2;
        u64 v3 = ((u64)obits(s3m + fn2_3) << 32) | (unsigned)i3;
        atomicMin(&g_best[b * Pn + pbase],     v0);
        atomicMin(&g_best[b * Pn + pbase + 1], v1);
        atomicMin(&g_best[b * Pn + pbase + 2], v2);
        atomicMin(&g_best[b * Pn + pbase + 3], v3);
    }
}

// ---------------------------------------------------------------------------
__global__ void finalize_kernel(float* __restrict__ out, int out_size) {
    int t = blockIdx.x * blockDim.x + threadIdx.x;
    unsigned thr = obits(BW2F);
    if (t < Bn * Pn) {
        u64 v = g_best[t];
        unsigned db = (unsigned)(v >> 32);
        unsigned kk = (unsigned)v;
        out[t] = (db < thr) ? (float)(kk + 1) : 0.0f;
    }
    if (t < Bn * Kn * Cn && (Bn * Pn + t) < out_size)
        out[Bn * Pn + t] = g_ms[ITERS][t];
}

extern "C" void kernel_launch(void* const* d_in, const int* in_sizes, int n_in,
                              void* d_out, int out_size) {
    const float* feat = (const float*)d_in[0];
    const void*  sidx = d_in[1];
    float* out = (float*)d_out;

    detect_idx_kernel<<<1, 256>>>(sidx);
    init_kernel<<<300, 256>>>(feat, sidx);

    dim3 grid(XB, Bn, ZS);
    for (int it = 0; it < ITERS; it++) {
        scan_kernel<<<grid, TPB>>>(feat, it);
        update_kernel<<<1, 512>>>(it);
    }
    scan_kernel<<<grid, TPB>>>(feat, ITERS);   // label pass

    finalize_kernel<<<(Bn * Pn + 255) / 256, 256>>>(out, out_size);
}

// round 8
// speedup vs baseline: 4.8517x; 1.6732x over previous
#include <cuda_runtime.h>

#define Bn 4
#define Cn 16
#define Kn 100
#define Pn 76800
#define ITERS 10
#define BW2F ((float)(0.16*0.16))

#define TPB 128
#define IPT 4                    // 4 points/thread
#define XB  (Pn/(TPB*IPT))       // 150
#define ZS  4
#define KQ  (Kn/ZS)              // 25
#define MSTR 20                  // floats per k: {-2m x16, mn2, 0, pad2}
#define UPB 4                    // update blocks

typedef unsigned long long u64;

// ---- device scratch (static; no allocations) ----
__device__ float g_ms[Bn*Kn*Cn];          // current means (in-place)
__device__ float g_prep[Bn*Kn*MSTR];      // {-2m, mn2} table for current means
__device__ float g_num[Bn*Kn*Cn];
__device__ float g_den[Bn*Kn];
__device__ u64   g_best[Bn*Pn];
__device__ int   g_is64;
__device__ int   g_conv;                   // latched fixed-point flag
__device__ int   g_sameCnt[ITERS];
__device__ int   g_done[ITERS];

// ---- packed f32x2 helpers ----
__device__ __forceinline__ u64 pk2(float lo, float hi) {
    u64 r; asm("mov.b64 %0,{%1,%2};" : "=l"(r) : "f"(lo), "f"(hi)); return r;
}
__device__ __forceinline__ void up2(u64 v, float& lo, float& hi) {
    asm("mov.b64 {%0,%1},%2;" : "=f"(lo), "=f"(hi) : "l"(v));
}
__device__ __forceinline__ u64 f2fma(u64 a, u64 b, u64 c) {
    u64 d; asm("fma.rn.f32x2 %0,%1,%2,%3;" : "=l"(d) : "l"(a), "l"(b), "l"(c)); return d;
}
__device__ __forceinline__ u64 f2mul(u64 a, u64 b) {
    u64 d; asm("mul.rn.f32x2 %0,%1,%2;" : "=l"(d) : "l"(a), "l"(b)); return d;
}
__device__ __forceinline__ unsigned obits(float f) {
    unsigned u = __float_as_uint(f);
    return (u & 0x80000000u) ? ~u : (u | 0x80000000u);
}

// ---------------------------------------------------------------------------
__global__ void detect_idx_kernel(const void* idxraw) {
    __shared__ int bad;
    if (threadIdx.x == 0) bad = 0;
    __syncthreads();
    const long long* p = (const long long*)idxraw;
    for (int i = threadIdx.x; i < 200; i += blockDim.x) {
        long long v = p[i];
        if (v < 0 || v >= (long long)Pn) bad = 1;
    }
    __syncthreads();
    if (threadIdx.x == 0) g_is64 = bad ? 0 : 1;
}

// ---------------------------------------------------------------------------
// Reset all state (graph replays), gather seed means, build prep.
// ---------------------------------------------------------------------------
__global__ void init_kernel(const float* __restrict__ feat,
                            const void* __restrict__ idxraw) {
    int t = blockIdx.x * blockDim.x + threadIdx.x;
    int stride = gridDim.x * blockDim.x;
    if (t == 0) g_conv = 0;
    if (t < ITERS) { g_sameCnt[t] = 0; g_done[t] = 0; }
    for (int i = t; i < Bn * Pn; i += stride) g_best[i] = ~0ull;
    for (int i = t; i < Bn * Kn * Cn; i += stride) g_num[i] = 0.0f;
    for (int i = t; i < Bn * Kn; i += stride) g_den[i] = 0.0f;

    if (t < Bn * Kn) {
        int b = t / Kn;
        long long idx;
        if (g_is64) idx = ((const long long*)idxraw)[t];
        else        idx = (long long)((const int*)idxraw)[t];
        const float* fb = feat + (size_t)b * Cn * Pn + (size_t)idx;
        float mn2 = 0.0f;
#pragma unroll
        for (int c = 0; c < Cn; c++) {
            float m = fb[(size_t)c * Pn];
            g_ms[t * Cn + c] = m;
            g_prep[t * MSTR + c] = -2.0f * m;
            mn2 += m * m;
        }
        g_prep[t * MSTR + 16] = mn2;
        g_prep[t * MSTR + 17] = 0.0f;
    }
}

// ---------------------------------------------------------------------------
// In-place mean update. Early-out once converged. Zeroes num/den after use.
// Last block latches g_conv when all clusters are bitwise unchanged.
// ---------------------------------------------------------------------------
__global__ void update_kernel(int it) {
    if (g_conv) return;
    __shared__ int s_same;
    int tl = threadIdx.x;
    if (tl == 0) s_same = 0;
    __syncthreads();
    int t = blockIdx.x * blockDim.x + tl;
    if (t < Bn * Kn) {
        float den = g_den[t];
        float dm = fmaxf(den, 1.0f);
        bool pos = den > 0.0f;
        bool same = true;
        float mn2 = 0.0f;
#pragma unroll
        for (int c = 0; c < Cn; c++) {
            float old = g_ms[t * Cn + c];
            float nm = pos ? (g_num[t * Cn + c] / dm) : old;
            g_ms[t * Cn + c] = nm;
            g_prep[t * MSTR + c] = -2.0f * nm;
            mn2 += nm * nm;
            same = same && (__float_as_uint(nm) == __float_as_uint(old));
            g_num[t * Cn + c] = 0.0f;          // ready for next scan
        }
        g_prep[t * MSTR + 16] = mn2;
        g_prep[t * MSTR + 17] = 0.0f;
        g_den[t] = 0.0f;
        if (same) atomicAdd(&s_same, 1);
    }
    __syncthreads();
    if (tl == 0) {
        atomicAdd(&g_sameCnt[it], s_same);
        __threadfence();
        int d = atomicAdd(&g_done[it], 1);
        if (d == gridDim.x - 1 && g_sameCnt[it] == Bn * Kn) g_conv = 1;
    }
}

// single-chain shifted distance: s = mn2 + sum_c f_c * (-2 m_c)
__device__ __forceinline__ float dchain1(const u64 (&f)[8],
                                         ulonglong2 mA, ulonglong2 mB,
                                         ulonglong2 mC, ulonglong2 mD,
                                         u64 mnz) {
    u64 v = f2fma(f[0], mA.x, mnz);
    v = f2fma(f[1], mA.y, v);
    v = f2fma(f[2], mB.x, v);
    v = f2fma(f[3], mB.y, v);
    v = f2fma(f[4], mC.x, v);
    v = f2fma(f[5], mC.y, v);
    v = f2fma(f[6], mD.x, v);
    v = f2fma(f[7], mD.y, v);
    float lo, hi; up2(v, lo, hi);
    return lo + hi;
}

// rare slow path: rescan all KQ means for one point, exact hit atomics
__device__ __noinline__ void rescan(const u64 (&f)[8], float thr,
                                    const float* s_m, int b, int k0) {
    for (int kl = 0; kl < KQ; kl++) {
        const ulonglong2* mp = (const ulonglong2*)&s_m[kl * MSTR];
        u64 mnz = *(const u64*)&s_m[kl * MSTR + 16];
        float s = dchain1(f, mp[0], mp[1], mp[2], mp[3], mnz);
        if (s < thr) {
            int kg = k0 + kl;
            atomicAdd(&g_den[b * Kn + kg], 1.0f);
#pragma unroll
            for (int j = 0; j < 8; j++) {
                float v0, v1; up2(f[j], v0, v1);
                atomicAdd(&g_num[(b * Kn + kg) * Cn + 2 * j],     v0);
                atomicAdd(&g_num[(b * Kn + kg) * Cn + 2 * j + 1], v1);
            }
        }
    }
}

// ---------------------------------------------------------------------------
// Scan pass over current means in g_prep.
//   iter<ITERS: accumulate into num/den (skipped once converged)
//   iter==ITERS: label pass (always runs)
// ---------------------------------------------------------------------------
__global__ void __launch_bounds__(TPB, 5)
scan_kernel(const float* __restrict__ feat, int iter) {
    if (iter > 0 && iter < ITERS && g_conv) return;   // fixed point reached

    __shared__ __align__(16) float s_m[KQ * MSTR];
    const int b = blockIdx.y;
    const int k0 = blockIdx.z * KQ;

    // copy this quarter's prep table (contiguous, 125 float4)
    {
        const float4* src = (const float4*)&g_prep[(b * Kn + k0) * MSTR];
        float4* dst = (float4*)s_m;
        for (int i = threadIdx.x; i < KQ * MSTR / 4; i += TPB)
            dst[i] = src[i];
    }
    __syncthreads();

    // ---- load 4 consecutive points; transpose to channel-packed pairs ----
    const int pbase = blockIdx.x * (TPB * IPT) + 4 * threadIdx.x;
    const float4* fb4 = (const float4*)(feat + (size_t)b * Cn * Pn + pbase);
    u64 f0[8], f1[8], f2[8], f3[8];
#pragma unroll
    for (int c = 0; c < Cn; c += 2) {
        float4 va = fb4[(size_t)c * (Pn / 4)];
        float4 vb = fb4[(size_t)(c + 1) * (Pn / 4)];
        f0[c / 2] = pk2(va.x, vb.x);
        f1[c / 2] = pk2(va.y, vb.y);
        f2[c / 2] = pk2(va.z, vb.z);
        f3[c / 2] = pk2(va.w, vb.w);
    }
    float fn2_0, fn2_1, fn2_2, fn2_3;
    {
        u64 q0 = f2mul(f0[0], f0[0]), q1 = f2mul(f1[0], f1[0]);
        u64 q2 = f2mul(f2[0], f2[0]), q3 = f2mul(f3[0], f3[0]);
#pragma unroll
        for (int j = 1; j < 8; j++) {
            q0 = f2fma(f0[j], f0[j], q0);
            q1 = f2fma(f1[j], f1[j], q1);
            q2 = f2fma(f2[j], f2[j], q2);
            q3 = f2fma(f3[j], f3[j], q3);
        }
        float lo, hi;
        up2(q0, lo, hi); fn2_0 = lo + hi;
        up2(q1, lo, hi); fn2_1 = lo + hi;
        up2(q2, lo, hi); fn2_2 = lo + hi;
        up2(q3, lo, hi); fn2_3 = lo + hi;
    }
    const float t0 = BW2F - fn2_0, t1 = BW2F - fn2_1;
    const float t2 = BW2F - fn2_2, t3 = BW2F - fn2_3;

    const bool lab = (iter == ITERS);
    float s0m = 3.4e38f, s1m = 3.4e38f, s2m = 3.4e38f, s3m = 3.4e38f;
    int i0 = 0, i1 = 0, i2 = 0, i3 = 0;

#pragma unroll 5
    for (int kl = 0; kl < KQ; kl++) {
        const ulonglong2* mp = (const ulonglong2*)&s_m[kl * MSTR];
        ulonglong2 mA = mp[0], mB = mp[1], mC = mp[2], mD = mp[3];
        u64 mnz = *(const u64*)&s_m[kl * MSTR + 16];
        float s0 = dchain1(f0, mA, mB, mC, mD, mnz);
        float s1 = dchain1(f1, mA, mB, mC, mD, mnz);
        float s2 = dchain1(f2, mA, mB, mC, mD, mnz);
        float s3 = dchain1(f3, mA, mB, mC, mD, mnz);
        if (!lab) {
            s0m = fminf(s0m, s0);
            s1m = fminf(s1m, s1);
            s2m = fminf(s2m, s2);
            s3m = fminf(s3m, s3);
        } else {
            if (s0 < s0m) { s0m = s0; i0 = k0 + kl; }
            if (s1 < s1m) { s1m = s1; i1 = k0 + kl; }
            if (s2 < s2m) { s2m = s2; i2 = k0 + kl; }
            if (s3 < s3m) { s3m = s3; i3 = k0 + kl; }
        }
    }

    if (!lab) {
        if (s0m < t0) rescan(f0, t0, s_m, b, k0);
        if (s1m < t1) rescan(f1, t1, s_m, b, k0);
        if (s2m < t2) rescan(f2, t2, s_m, b, k0);
        if (s3m < t3) rescan(f3, t3, s_m, b, k0);
    } else {
        u64 v0 = ((u64)obits(s0m + fn2_0) << 32) | (unsigned)i0;
        u64 v1 = ((u64)obits(s1m + fn2_1) << 32) | (unsigned)i1;
        u64 v2 = ((u64)obits(s2m + fn2_2) << 32) | (unsigned)i2;
        u64 v3 = ((u64)obits(s3m + fn2_3) << 32) | (unsigned)i3;
        atomicMin(&g_best[b * Pn + pbase],     v0);
        atomicMin(&g_best[b * Pn + pbase + 1], v1);
        atomicMin(&g_best[b * Pn + pbase + 2], v2);
        atomicMin(&g_best[b * Pn + pbase + 3], v3);
    }
}

// ---------------------------------------------------------------------------
__global__ void finalize_kernel(float* __restrict__ out, int out_size) {
    int t = blockIdx.x * blockDim.x + threadIdx.x;
    unsigned thr = obits(BW2F);
    if (t < Bn * Pn) {
        u64 v = g_best[t];
        unsigned db = (unsigned)(v >> 32);
        unsigned kk = (unsigned)v;
        out[t] = (db < thr) ? (float)(kk + 1) : 0.0f;
    }
    if (t < Bn * Kn * Cn && (Bn * Pn + t) < out_size)
        out[Bn * Pn + t] = g_ms[t];
}

extern "C" void kernel_launch(void* const* d_in, const int* in_sizes, int n_in,
                              void* d_out, int out_size) {
    const float* feat = (const float*)d_in[0];
    const void*  sidx = d_in[1];
    float* out = (float*)d_out;

    detect_idx_kernel<<<1, 256>>>(sidx);
    init_kernel<<<300, 256>>>(feat, sidx);

    dim3 grid(XB, Bn, ZS);
    for (int it = 0; it < ITERS; it++) {
        scan_kernel<<<grid, TPB>>>(feat, it);
        update_kernel<<<UPB, TPB>>>(it);
    }
    scan_kernel<<<grid, TPB>>>(feat, ITERS);   // label pass

    finalize_kernel<<<(Bn * Pn + 255) / 256, 256>>>(out, out_size);
}

// round 9
// speedup vs baseline: 5.0373x; 1.0383x over previous
#include <cuda_runtime.h>

#define Bn 4
#define Cn 16
#define Kn 100
#define Pn 76800
#define ITERS 10
#define BW2F ((float)(0.16*0.16))

#define TPB 128
#define IPT 4                    // 4 points/thread
#define XB  (Pn/(TPB*IPT))       // 150 -> grid (150,4) = 600 blocks = 1 wave @5/SM
#define MSTR 20                  // floats per k: {-2m x16, mn2, 0, pad2}

typedef unsigned long long u64;

// ---- device scratch (static; no allocations) ----
__device__ float g_ms[ITERS+1][Bn*Kn*Cn];   // [0]=seeds, [it]=iter means, [ITERS]=final latch
__device__ float g_num[ITERS][Bn*Kn*Cn];
__device__ float g_den[ITERS][Bn*Kn];
__device__ int   g_bconv[Bn];               // per-batch fixed-point latch

// ---- packed f32x2 helpers ----
__device__ __forceinline__ u64 pk2(float lo, float hi) {
    u64 r; asm("mov.b64 %0,{%1,%2};" : "=l"(r) : "f"(lo), "f"(hi)); return r;
}
__device__ __forceinline__ void up2(u64 v, float& lo, float& hi) {
    asm("mov.b64 {%0,%1},%2;" : "=f"(lo), "=f"(hi) : "l"(v));
}
__device__ __forceinline__ u64 f2fma(u64 a, u64 b, u64 c) {
    u64 d; asm("fma.rn.f32x2 %0,%1,%2,%3;" : "=l"(d) : "l"(a), "l"(b), "l"(c)); return d;
}
__device__ __forceinline__ u64 f2mul(u64 a, u64 b) {
    u64 d; asm("mul.rn.f32x2 %0,%1,%2;" : "=l"(d) : "l"(a), "l"(b)); return d;
}

// ---------------------------------------------------------------------------
// Single-block init: int64/int32 detection, zero accumulators, gather seeds.
// ---------------------------------------------------------------------------
__global__ void init_kernel(const float* __restrict__ feat,
                            const void* __restrict__ idxraw) {
    __shared__ int s_is64;
    int t = threadIdx.x;
    if (t == 0) s_is64 = 1;
    __syncthreads();
    // first 1600 bytes valid under both layouts; int32 data interpreted as
    // int64 is almost surely out of [0,Pn)
    if (t < 200) {
        long long v = ((const long long*)idxraw)[t];
        if (v < 0 || v >= (long long)Pn) s_is64 = 0;  // benign race, same value
    }
    __syncthreads();

    float* num0 = &g_num[0][0];
    for (int i = t; i < ITERS * Bn * Kn * Cn; i += blockDim.x) num0[i] = 0.0f;
    float* den0 = &g_den[0][0];
    for (int i = t; i < ITERS * Bn * Kn; i += blockDim.x) den0[i] = 0.0f;
    if (t < Bn) g_bconv[t] = 0;

    if (t < Bn * Kn) {
        int b = t / Kn;
        long long idx = s_is64 ? ((const long long*)idxraw)[t]
                               : (long long)((const int*)idxraw)[t];
        const float* fb = feat + (size_t)b * Cn * Pn + (size_t)idx;
#pragma unroll
        for (int c = 0; c < Cn; c++)
            g_ms[0][t * Cn + c] = fb[(size_t)c * Pn];
    }
}

// single-chain shifted distance: s = mn2 + sum_c f_c * (-2 m_c)
__device__ __forceinline__ float dchain1(const u64 (&f)[8],
                                         ulonglong2 mA, ulonglong2 mB,
                                         ulonglong2 mC, ulonglong2 mD,
                                         u64 mnz) {
    u64 v = f2fma(f[0], mA.x, mnz);
    v = f2fma(f[1], mA.y, v);
    v = f2fma(f[2], mB.x, v);
    v = f2fma(f[3], mB.y, v);
    v = f2fma(f[4], mC.x, v);
    v = f2fma(f[5], mC.y, v);
    v = f2fma(f[6], mD.x, v);
    v = f2fma(f[7], mD.y, v);
    float lo, hi; up2(v, lo, hi);
    return lo + hi;
}

// rare slow path: rescan all Kn means for one point, exact hit atomics
__device__ __noinline__ void rescan(const u64 (&f)[8], float thr,
                                    const float* s_m, int b, int it) {
    for (int kl = 0; kl < Kn; kl++) {
        const ulonglong2* mp = (const ulonglong2*)&s_m[kl * MSTR];
        u64 mnz = *(const u64*)&s_m[kl * MSTR + 16];
        float s = dchain1(f, mp[0], mp[1], mp[2], mp[3], mnz);
        if (s < thr) {
            int kg = b * Kn + kl;
            atomicAdd(&g_den[it][kg], 1.0f);
#pragma unroll
            for (int j = 0; j < 8; j++) {
                float v0, v1; up2(f[j], v0, v1);
                atomicAdd(&g_num[it][kg * Cn + 2 * j],     v0);
                atomicAdd(&g_num[it][kg * Cn + 2 * j + 1], v1);
            }
        }
    }
}

// ---------------------------------------------------------------------------
// Fused pass: prologue (mean update + per-batch fixed-point latch) + scan.
//   it in [0,ITERS): accumulate into num/den[it]; skip once batch converged
//   it == ITERS:     label pass; writes labels + means directly to out
// ---------------------------------------------------------------------------
__global__ void __launch_bounds__(TPB, 5)
scan_kernel(const float* __restrict__ feat, float* __restrict__ out,
            int it, int out_size) {
    const int b = blockIdx.y;
    const bool lab = (it == ITERS);
    const bool conv = (it > 0) && (g_bconv[b] != 0);
    if (conv && !lab) return;                     // fixed point: nothing to do

    __shared__ __align__(16) float s_m[Kn * MSTR];
    __shared__ int s_cnt;
    if (threadIdx.x == 0) s_cnt = 0;
    __syncthreads();

    // ---- prologue: build {-2m, mn2} table (and detect fixed point) ----
    if (threadIdx.x < Kn) {
        int t = b * Kn + threadIdx.x;
        float mn2 = 0.0f;
        if (it == 0 || conv) {
            const float* src = conv ? &g_ms[ITERS][t * Cn] : &g_ms[0][t * Cn];
#pragma unroll
            for (int c = 0; c < Cn; c++) {
                float m = src[c];
                s_m[threadIdx.x * MSTR + c] = -2.0f * m;
                mn2 += m * m;
            }
        } else {
            float den = g_den[it - 1][t];
            float dm = fmaxf(den, 1.0f);
            bool pos = den > 0.0f;
            bool same = true;
#pragma unroll
            for (int c = 0; c < Cn; c++) {
                float old = g_ms[it - 1][t * Cn + c];
                float nm = pos ? (g_num[it - 1][t * Cn + c] / dm) : old;
                s_m[threadIdx.x * MSTR + c] = -2.0f * nm;
                mn2 += nm * nm;
                same = same && (__float_as_uint(nm) == __float_as_uint(old));
            }
            if (same) atomicAdd(&s_cnt, 1);
        }
        s_m[threadIdx.x * MSTR + 16] = mn2;
        s_m[threadIdx.x * MSTR + 17] = 0.0f;
    }
    __syncthreads();

    if (!lab && it > 0) {
        if (s_cnt == Kn) {
            // fixed point reached NOW: latch, snapshot final means, skip scan
            if (blockIdx.x == 0) {
                for (int i = threadIdx.x; i < Kn * Cn; i += TPB)
                    g_ms[ITERS][b * Kn * Cn + i] =
                        -0.5f * s_m[(i / Cn) * MSTR + (i % Cn)];
                __threadfence();
                if (threadIdx.x == 0) g_bconv[b] = 1;
            }
            return;
        }
        // persist means[it] for the next prologue
        if (blockIdx.x == 0) {
            for (int i = threadIdx.x; i < Kn * Cn; i += TPB)
                g_ms[it][b * Kn * Cn + i] =
                    -0.5f * s_m[(i / Cn) * MSTR + (i % Cn)];
        }
    }

    // ---- load 4 consecutive points; transpose to channel-packed pairs ----
    const int pbase = blockIdx.x * (TPB * IPT) + 4 * threadIdx.x;
    const float4* fb4 = (const float4*)(feat + (size_t)b * Cn * Pn + pbase);
    u64 f0[8], f1[8], f2[8], f3[8];
#pragma unroll
    for (int c = 0; c < Cn; c += 2) {
        float4 va = fb4[(size_t)c * (Pn / 4)];
        float4 vb = fb4[(size_t)(c + 1) * (Pn / 4)];
        f0[c / 2] = pk2(va.x, vb.x);
        f1[c / 2] = pk2(va.y, vb.y);
        f2[c / 2] = pk2(va.z, vb.z);
        f3[c / 2] = pk2(va.w, vb.w);
    }
    float fn2_0, fn2_1, fn2_2, fn2_3;
    {
        u64 q0 = f2mul(f0[0], f0[0]), q1 = f2mul(f1[0], f1[0]);
        u64 q2 = f2mul(f2[0], f2[0]), q3 = f2mul(f3[0], f3[0]);
#pragma unroll
        for (int j = 1; j < 8; j++) {
            q0 = f2fma(f0[j], f0[j], q0);
            q1 = f2fma(f1[j], f1[j], q1);
            q2 = f2fma(f2[j], f2[j], q2);
            q3 = f2fma(f3[j], f3[j], q3);
        }
        float lo, hi;
        up2(q0, lo, hi); fn2_0 = lo + hi;
        up2(q1, lo, hi); fn2_1 = lo + hi;
        up2(q2, lo, hi); fn2_2 = lo + hi;
        up2(q3, lo, hi); fn2_3 = lo + hi;
    }
    const float t0 = BW2F - fn2_0, t1 = BW2F - fn2_1;
    const float t2 = BW2F - fn2_2, t3 = BW2F - fn2_3;

    float s0m = 3.4e38f, s1m = 3.4e38f, s2m = 3.4e38f, s3m = 3.4e38f;
    int i0 = 0, i1 = 0, i2 = 0, i3 = 0;

#pragma unroll 4
    for (int kl = 0; kl < Kn; kl++) {
        const ulonglong2* mp = (const ulonglong2*)&s_m[kl * MSTR];
        ulonglong2 mA = mp[0], mB = mp[1], mC = mp[2], mD = mp[3];
        u64 mnz = *(const u64*)&s_m[kl * MSTR + 16];
        float s0 = dchain1(f0, mA, mB, mC, mD, mnz);
        float s1 = dchain1(f1, mA, mB, mC, mD, mnz);
        float s2 = dchain1(f2, mA, mB, mC, mD, mnz);
        float s3 = dchain1(f3, mA, mB, mC, mD, mnz);
        if (!lab) {
            s0m = fminf(s0m, s0);
            s1m = fminf(s1m, s1);
            s2m = fminf(s2m, s2);
            s3m = fminf(s3m, s3);
        } else {
            if (s0 < s0m) { s0m = s0; i0 = kl; }
            if (s1 < s1m) { s1m = s1; i1 = kl; }
            if (s2 < s2m) { s2m = s2; i2 = kl; }
            if (s3 < s3m) { s3m = s3; i3 = kl; }
        }
    }

    if (!lab) {
        if (s0m < t0) rescan(f0, t0, s_m, b, it);
        if (s1m < t1) rescan(f1, t1, s_m, b, it);
        if (s2m < t2) rescan(f2, t2, s_m, b, it);
        if (s3m < t3) rescan(f3, t3, s_m, b, it);
    } else {
        // direct label write: full-K argmin per point, first-min tie-break
        float* ob = out + (size_t)b * Pn + pbase;
        ob[0] = (s0m < t0) ? (float)(i0 + 1) : 0.0f;
        ob[1] = (s1m < t1) ? (float)(i1 + 1) : 0.0f;
        ob[2] = (s2m < t2) ? (float)(i2 + 1) : 0.0f;
        ob[3] = (s3m < t3) ? (float)(i3 + 1) : 0.0f;
        // means tail written once per batch
        if (blockIdx.x == 0) {
            for (int i = threadIdx.x; i < Kn * Cn; i += TPB) {
                int o = Bn * Pn + b * Kn * Cn + i;
                if (o < out_size)
                    out[o] = -0.5f * s_m[(i / Cn) * MSTR + (i % Cn)];
            }
        }
    }
}

extern "C" void kernel_launch(void* const* d_in, const int* in_sizes, int n_in,
                              void* d_out, int out_size) {
    const float* feat = (const float*)d_in[0];
    const void*  sidx = d_in[1];
    float* out = (float*)d_out;

    init_kernel<<<1, 1024>>>(feat, sidx);

    dim3 grid(XB, Bn);
    for (int it = 0; it <= ITERS; it++)
        scan_kernel<<<grid, TPB>>>(feat, out, it, out_size);
}